// round 1
// baseline (speedup 1.0000x reference)
#include <cuda_runtime.h>

#define SEQ 4096
#define DMODEL 1024
#define NHEADS 16
#define HDIM 64
#define QKV_N 3072

// Scratch (static device arrays — no allocation)
__device__ float g_qkv[SEQ * QKV_N];   // [S, 3D]: q | k | v
__device__ float g_ctx[SEQ * DMODEL];  // [S, D]

// ----------------------------------------------------------------------------
// Tiled SGEMM: C[M,N] = A[M,K] @ B[K,N] + bias[N]
// BM=BN=128, BK=16, 256 threads, 8x8 per-thread microtile.
// All dims here are multiples of the tile sizes (4096/1024/3072).
// ----------------------------------------------------------------------------
__global__ void gemm_bias_kernel(const float* __restrict__ A,
                                 const float* __restrict__ B,
                                 const float* __restrict__ bias,
                                 float* __restrict__ C,
                                 int M, int N, int K) {
    const int BM = 128, BN = 128, BK = 16;
    __shared__ float As[BK][BM];   // transposed A tile
    __shared__ float Bs[BK][BN];

    int tid = threadIdx.x;
    int bm = blockIdx.y, bn = blockIdx.x;
    int row0 = (tid / 16) * 8;
    int col0 = (tid % 16) * 8;

    float acc[8][8] = {};

    for (int k0 = 0; k0 < K; k0 += BK) {
        // Load A tile 128x16 (2048 floats = 512 float4, 2 per thread)
        #pragma unroll
        for (int i = 0; i < 2; i++) {
            int linear = tid + i * 256;       // float4 index
            int r  = linear / 4;              // 0..127
            int c4 = linear % 4;              // 0..3
            float4 v = *(const float4*)&A[(size_t)(bm * BM + r) * K + k0 + c4 * 4];
            As[c4 * 4 + 0][r] = v.x;
            As[c4 * 4 + 1][r] = v.y;
            As[c4 * 4 + 2][r] = v.z;
            As[c4 * 4 + 3][r] = v.w;
        }
        // Load B tile 16x128
        #pragma unroll
        for (int i = 0; i < 2; i++) {
            int linear = tid + i * 256;
            int r  = linear / 32;             // 0..15
            int c4 = linear % 32;             // 0..31
            *(float4*)&Bs[r][c4 * 4] =
                *(const float4*)&B[(size_t)(k0 + r) * N + bn * BN + c4 * 4];
        }
        __syncthreads();

        #pragma unroll
        for (int kk = 0; kk < BK; kk++) {
            float a[8], b[8];
            *(float4*)&a[0] = *(float4*)&As[kk][row0];
            *(float4*)&a[4] = *(float4*)&As[kk][row0 + 4];
            *(float4*)&b[0] = *(float4*)&Bs[kk][col0];
            *(float4*)&b[4] = *(float4*)&Bs[kk][col0 + 4];
            #pragma unroll
            for (int i = 0; i < 8; i++)
                #pragma unroll
                for (int j = 0; j < 8; j++)
                    acc[i][j] += a[i] * b[j];
        }
        __syncthreads();
    }

    // Epilogue: add bias, store
    float bv[8];
    #pragma unroll
    for (int j = 0; j < 8; j++) bv[j] = bias[bn * BN + col0 + j];

    #pragma unroll
    for (int i = 0; i < 8; i++) {
        float4 o0, o1;
        o0.x = acc[i][0] + bv[0]; o0.y = acc[i][1] + bv[1];
        o0.z = acc[i][2] + bv[2]; o0.w = acc[i][3] + bv[3];
        o1.x = acc[i][4] + bv[4]; o1.y = acc[i][5] + bv[5];
        o1.z = acc[i][6] + bv[6]; o1.w = acc[i][7] + bv[7];
        size_t base = (size_t)(bm * BM + row0 + i) * N + bn * BN + col0;
        *(float4*)&C[base]     = o0;
        *(float4*)&C[base + 4] = o1;
    }
}

// ----------------------------------------------------------------------------
// Flash-attention (causal), fp32. One CTA per (q-block of 64 rows, head).
// 256 threads = 16x16 grid; each thread owns a 4x4 score/output microtile.
// Online softmax; blocks strictly above the diagonal are skipped.
// ----------------------------------------------------------------------------
__global__ void attn_kernel() {
    const int BM = 64, BN = 64, P = HDIM + 1;  // pitch 65 -> conflict-free cols
    extern __shared__ float sm[];
    float* Qs = sm;                 // [64][65]
    float* Ks = Qs + BM * P;        // [64][65]
    float* Vs = Ks + BN * P;        // [64][65]
    float* Ps = Vs + BN * P;        // [64][65]

    int qb = blockIdx.x;            // 0..63
    int h  = blockIdx.y;            // 0..15
    int tid = threadIdx.x;
    int tx = tid % 16, ty = tid / 16;

    const int q_off = h * HDIM;
    const int k_off = DMODEL + h * HDIM;
    const int v_off = 2 * DMODEL + h * HDIM;

    // Load Q tile (64x64 = 1024 float4)
    for (int l = tid; l < 1024; l += 256) {
        int r  = l / 16;
        int c4 = (l % 16) * 4;
        const float* src = &g_qkv[(size_t)(qb * BM + r) * QKV_N + q_off + c4];
        float4 v = *(const float4*)src;
        Qs[r * P + c4 + 0] = v.x;
        Qs[r * P + c4 + 1] = v.y;
        Qs[r * P + c4 + 2] = v.z;
        Qs[r * P + c4 + 3] = v.w;
    }

    float o[4][4] = {};
    float mrow[4], lrow[4];
    #pragma unroll
    for (int i = 0; i < 4; i++) { mrow[i] = -1e30f; lrow[i] = 0.0f; }

    for (int jb = 0; jb <= qb; jb++) {
        // Load K, V tiles
        for (int l = tid; l < 1024; l += 256) {
            int r  = l / 16;
            int c4 = (l % 16) * 4;
            size_t grow = (size_t)(jb * BN + r) * QKV_N;
            float4 kv = *(const float4*)&g_qkv[grow + k_off + c4];
            Ks[r * P + c4 + 0] = kv.x;
            Ks[r * P + c4 + 1] = kv.y;
            Ks[r * P + c4 + 2] = kv.z;
            Ks[r * P + c4 + 3] = kv.w;
            float4 vv = *(const float4*)&g_qkv[grow + v_off + c4];
            Vs[r * P + c4 + 0] = vv.x;
            Vs[r * P + c4 + 1] = vv.y;
            Vs[r * P + c4 + 2] = vv.z;
            Vs[r * P + c4 + 3] = vv.w;
        }
        __syncthreads();

        // S = Q @ K^T * 1/sqrt(Hd)
        float s[4][4] = {};
        #pragma unroll 8
        for (int kk = 0; kk < HDIM; kk++) {
            float a[4], b[4];
            #pragma unroll
            for (int i = 0; i < 4; i++) a[i] = Qs[(ty * 4 + i) * P + kk];
            #pragma unroll
            for (int j = 0; j < 4; j++) b[j] = Ks[(tx * 4 + j) * P + kk];
            #pragma unroll
            for (int i = 0; i < 4; i++)
                #pragma unroll
                for (int j = 0; j < 4; j++)
                    s[i][j] += a[i] * b[j];
        }
        #pragma unroll
        for (int i = 0; i < 4; i++)
            #pragma unroll
            for (int j = 0; j < 4; j++)
                s[i][j] *= 0.125f;   // 1/sqrt(64)

        // Causal mask (only the diagonal block needs it)
        if (jb == qb) {
            #pragma unroll
            for (int i = 0; i < 4; i++) {
                int rloc = ty * 4 + i;
                #pragma unroll
                for (int j = 0; j < 4; j++) {
                    int cloc = tx * 4 + j;
                    if (cloc > rloc) s[i][j] = -1e30f;
                }
            }
        }

        // Row max over this block (reduce j locally, then across tx lanes)
        float mij[4];
        #pragma unroll
        for (int i = 0; i < 4; i++) {
            mij[i] = fmaxf(fmaxf(s[i][0], s[i][1]), fmaxf(s[i][2], s[i][3]));
            #pragma unroll
            for (int off = 8; off >= 1; off >>= 1)
                mij[i] = fmaxf(mij[i], __shfl_xor_sync(0xffffffffu, mij[i], off));
        }

        float rowsum[4] = {};
        #pragma unroll
        for (int i = 0; i < 4; i++) {
            float mnew  = fmaxf(mrow[i], mij[i]);
            float alpha = __expf(mrow[i] - mnew);
            #pragma unroll
            for (int j = 0; j < 4; j++) {
                float p = __expf(s[i][j] - mnew);
                Ps[(ty * 4 + i) * P + tx * 4 + j] = p;
                rowsum[i] += p;
            }
            #pragma unroll
            for (int off = 8; off >= 1; off >>= 1)
                rowsum[i] += __shfl_xor_sync(0xffffffffu, rowsum[i], off);
            lrow[i] = lrow[i] * alpha + rowsum[i];
            mrow[i] = mnew;
            #pragma unroll
            for (int j = 0; j < 4; j++) o[i][j] *= alpha;
        }
        __syncthreads();

        // O += P @ V
        #pragma unroll 8
        for (int kk = 0; kk < BN; kk++) {
            float a[4], b[4];
            #pragma unroll
            for (int i = 0; i < 4; i++) a[i] = Ps[(ty * 4 + i) * P + kk];
            #pragma unroll
            for (int j = 0; j < 4; j++) b[j] = Vs[kk * P + tx * 4 + j];
            #pragma unroll
            for (int i = 0; i < 4; i++)
                #pragma unroll
                for (int j = 0; j < 4; j++)
                    o[i][j] += a[i] * b[j];
        }
        __syncthreads();
    }

    // Normalize and write ctx
    #pragma unroll
    for (int i = 0; i < 4; i++) {
        float inv = 1.0f / lrow[i];
        int r = qb * BM + ty * 4 + i;
        #pragma unroll
        for (int j = 0; j < 4; j++)
            g_ctx[(size_t)r * DMODEL + h * HDIM + tx * 4 + j] = o[i][j] * inv;
    }
}

// ----------------------------------------------------------------------------
extern "C" void kernel_launch(void* const* d_in, const int* in_sizes, int n_in,
                              void* d_out, int out_size) {
    (void)in_sizes; (void)n_in; (void)out_size;
    const float* x     = (const float*)d_in[0];  // [1,4096,1024]
    const float* w_qkv = (const float*)d_in[1];  // [1024,3072]
    const float* b_qkv = (const float*)d_in[2];  // [3072]
    const float* w_out = (const float*)d_in[3];  // [1024,1024]
    const float* b_out = (const float*)d_in[4];  // [1024]
    float* out = (float*)d_out;                  // [1,4096,1024]

    float* qkv_ptr = nullptr;
    float* ctx_ptr = nullptr;
    cudaGetSymbolAddress((void**)&qkv_ptr, g_qkv);
    cudaGetSymbolAddress((void**)&ctx_ptr, g_ctx);

    const int ATTN_SMEM = 4 * 64 * (HDIM + 1) * (int)sizeof(float);  // 66560 B
    static bool attr_set = false;
    if (!attr_set) {
        cudaFuncSetAttribute(attn_kernel,
                             cudaFuncAttributeMaxDynamicSharedMemorySize, ATTN_SMEM);
        attr_set = true;
    }

    // 1) QKV projection: [4096,1024] @ [1024,3072] + b
    gemm_bias_kernel<<<dim3(QKV_N / 128, SEQ / 128), 256>>>(
        x, w_qkv, b_qkv, qkv_ptr, SEQ, QKV_N, DMODEL);

    // 2) Causal attention per (q-block, head)
    attn_kernel<<<dim3(SEQ / 64, NHEADS), 256, ATTN_SMEM>>>();

    // 3) Output projection: [4096,1024] @ [1024,1024] + b
    gemm_bias_kernel<<<dim3(DMODEL / 128, SEQ / 128), 256>>>(
        ctx_ptr, w_out, b_out, out, SEQ, DMODEL, DMODEL);
}

// round 2
// speedup vs baseline: 5.4142x; 5.4142x over previous
#include <cuda_runtime.h>

#define SEQ 4096
#define DMODEL 1024
#define NHEADS 16
#define HDIM 64
#define QKV_N 3072

// Scratch (static device arrays — no allocation)
__device__ float g_qkv[SEQ * QKV_N];   // [S, 3D]: q | k | v
__device__ float g_ctx[SEQ * DMODEL];  // [S, D]

// ---------------------------------------------------------------------------
// tf32 helpers
// ---------------------------------------------------------------------------
__device__ __forceinline__ unsigned f2tf(float f) {
    unsigned u;
    asm("cvt.rna.tf32.f32 %0, %1;" : "=r"(u) : "f"(f));
    return u;
}

__device__ __forceinline__ void mma_tf32(float c[4], const unsigned a[4], const unsigned b[2]) {
    asm volatile(
        "mma.sync.aligned.m16n8k8.row.col.f32.tf32.tf32.f32 "
        "{%0,%1,%2,%3},{%4,%5,%6,%7},{%8,%9},{%0,%1,%2,%3};"
        : "+f"(c[0]), "+f"(c[1]), "+f"(c[2]), "+f"(c[3])
        : "r"(a[0]), "r"(a[1]), "r"(a[2]), "r"(a[3]), "r"(b[0]), "r"(b[1]));
}

// ---------------------------------------------------------------------------
// TF32 tensor-core GEMM: C[M,N] = A[M,K] @ B[K,N] + bias[N]
// BM=128, BN=128, BK=32. 256 threads = 8 warps as 4(m) x 2(n); warp tile 32x64.
// ---------------------------------------------------------------------------
#define GAP 36   // A smem pitch: (4g+tig) unique mod 32 -> conflict-free a-frags
#define GBP 136  // B smem pitch: (8tig+g) unique mod 32 -> conflict-free b-frags

__global__ __launch_bounds__(256) void gemm_tf32_kernel(
    const float* __restrict__ A, const float* __restrict__ B,
    const float* __restrict__ bias, float* __restrict__ C,
    int M, int N, int K) {
    const int BM = 128, BN = 128, BK = 32;
    __shared__ unsigned As[BM][GAP];     // [m][k], pitch 36
    __shared__ unsigned Bs[BK][GBP];     // [k][n], pitch 136

    int tid = threadIdx.x;
    int wid = tid >> 5, lane = tid & 31;
    int g = lane >> 2, tig = lane & 3;
    int warp_m = wid >> 1, warp_n = wid & 1;
    int bm = blockIdx.y * BM, bn = blockIdx.x * BN;

    float acc[2][8][4];
    #pragma unroll
    for (int mc = 0; mc < 2; mc++)
        #pragma unroll
        for (int nc = 0; nc < 8; nc++)
            #pragma unroll
            for (int i = 0; i < 4; i++) acc[mc][nc][i] = 0.0f;

    for (int k0 = 0; k0 < K; k0 += BK) {
        __syncthreads();
        // A tile: 128 rows x 32 k = 1024 float4
        #pragma unroll
        for (int i = 0; i < 4; i++) {
            int linear = tid + i * 256;
            int r  = linear >> 3;          // 0..127
            int c4 = (linear & 7) * 4;     // 0..28
            float4 v = *(const float4*)&A[(size_t)(bm + r) * K + k0 + c4];
            As[r][c4 + 0] = f2tf(v.x);
            As[r][c4 + 1] = f2tf(v.y);
            As[r][c4 + 2] = f2tf(v.z);
            As[r][c4 + 3] = f2tf(v.w);
        }
        // B tile: 32 rows x 128 n = 1024 float4 (vectorized smem store)
        #pragma unroll
        for (int i = 0; i < 4; i++) {
            int linear = tid + i * 256;
            int r  = linear >> 5;          // 0..31
            int c4 = (linear & 31) * 4;    // 0..124
            float4 v = *(const float4*)&B[(size_t)(k0 + r) * N + bn + c4];
            uint4 u;
            u.x = f2tf(v.x); u.y = f2tf(v.y); u.z = f2tf(v.z); u.w = f2tf(v.w);
            *(uint4*)&Bs[r][c4] = u;
        }
        __syncthreads();

        #pragma unroll
        for (int kc = 0; kc < 4; kc++) {
            unsigned a[2][4];
            #pragma unroll
            for (int mc = 0; mc < 2; mc++) {
                int row = warp_m * 32 + mc * 16;
                a[mc][0] = As[row + g][kc * 8 + tig];
                a[mc][1] = As[row + g + 8][kc * 8 + tig];
                a[mc][2] = As[row + g][kc * 8 + tig + 4];
                a[mc][3] = As[row + g + 8][kc * 8 + tig + 4];
            }
            #pragma unroll
            for (int nc = 0; nc < 8; nc++) {
                unsigned b[2];
                int col = warp_n * 64 + nc * 8 + g;
                b[0] = Bs[kc * 8 + tig][col];
                b[1] = Bs[kc * 8 + tig + 4][col];
                mma_tf32(acc[0][nc], a[0], b);
                mma_tf32(acc[1][nc], a[1], b);
            }
        }
    }

    // Epilogue: bias + store (C-frag layout)
    #pragma unroll
    for (int nc = 0; nc < 8; nc++) {
        int col = bn + warp_n * 64 + nc * 8 + 2 * tig;
        float bv0 = bias[col], bv1 = bias[col + 1];
        #pragma unroll
        for (int mc = 0; mc < 2; mc++) {
            int row = bm + warp_m * 32 + mc * 16 + g;
            float2 o0 = make_float2(acc[mc][nc][0] + bv0, acc[mc][nc][1] + bv1);
            float2 o1 = make_float2(acc[mc][nc][2] + bv0, acc[mc][nc][3] + bv1);
            *(float2*)&C[(size_t)row * N + col]       = o0;
            *(float2*)&C[(size_t)(row + 8) * N + col] = o1;
        }
    }
}

// ---------------------------------------------------------------------------
// Flash attention (causal) with tf32 mma. One CTA per (q-block 64, head).
// 128 threads = 4 warps; warp w owns rows 16w..16w+15 of the block.
// ---------------------------------------------------------------------------
#define QP 68   // Qs/Ks/Ps pitch: (4g+tig) unique mod 32
#define VP 72   // Vs pitch: (8tig+g) unique mod 32

__global__ __launch_bounds__(128) void attn_tf32_kernel() {
    extern __shared__ unsigned sm[];
    unsigned* Qs = sm;                 // [64][68]  row=q, col=hd
    unsigned* Ks = Qs + 64 * QP;       // [64][68]  row=kpos, col=hd
    unsigned* Ps = Ks + 64 * QP;       // [64][68]  row=q, col=kpos
    unsigned* Vs = Ps + 64 * QP;       // [64][72]  row=kpos, col=hd

    int qb = gridDim.x - 1 - blockIdx.x;  // longest CTAs first
    int h  = blockIdx.y;
    int tid = threadIdx.x;
    int wid = tid >> 5, lane = tid & 31;
    int g = lane >> 2, tig = lane & 3;
    int row0 = wid * 16;

    const int q_off = h * HDIM;
    const int k_off = DMODEL + h * HDIM;
    const int v_off = 2 * DMODEL + h * HDIM;

    // Load Q tile (64x64 = 1024 float4, 8 per thread), tf32-converted
    #pragma unroll
    for (int i = 0; i < 8; i++) {
        int linear = tid + i * 128;
        int r  = linear >> 4;
        int c4 = (linear & 15) * 4;
        float4 v = *(const float4*)&g_qkv[(size_t)(qb * 64 + r) * QKV_N + q_off + c4];
        Qs[r * QP + c4 + 0] = f2tf(v.x);
        Qs[r * QP + c4 + 1] = f2tf(v.y);
        Qs[r * QP + c4 + 2] = f2tf(v.z);
        Qs[r * QP + c4 + 3] = f2tf(v.w);
    }

    float o[8][4];
    #pragma unroll
    for (int nc = 0; nc < 8; nc++)
        #pragma unroll
        for (int i = 0; i < 4; i++) o[nc][i] = 0.0f;
    float m0 = -1e30f, m1 = -1e30f, l0 = 0.0f, l1 = 0.0f;

    for (int jb = 0; jb <= qb; jb++) {
        __syncthreads();  // prior PV reads of Vs / loads of Ks done
        // Load K and V tiles
        #pragma unroll
        for (int i = 0; i < 8; i++) {
            int linear = tid + i * 128;
            int r  = linear >> 4;
            int c4 = (linear & 15) * 4;
            size_t grow = (size_t)(jb * 64 + r) * QKV_N;
            float4 kv = *(const float4*)&g_qkv[grow + k_off + c4];
            Ks[r * QP + c4 + 0] = f2tf(kv.x);
            Ks[r * QP + c4 + 1] = f2tf(kv.y);
            Ks[r * QP + c4 + 2] = f2tf(kv.z);
            Ks[r * QP + c4 + 3] = f2tf(kv.w);
            float4 vv = *(const float4*)&g_qkv[grow + v_off + c4];
            Vs[r * VP + c4 + 0] = f2tf(vv.x);
            Vs[r * VP + c4 + 1] = f2tf(vv.y);
            Vs[r * VP + c4 + 2] = f2tf(vv.z);
            Vs[r * VP + c4 + 3] = f2tf(vv.w);
        }
        __syncthreads();

        // ---- S = Q @ K^T (16x64 per warp) ----
        float s[8][4];
        #pragma unroll
        for (int nc = 0; nc < 8; nc++)
            #pragma unroll
            for (int i = 0; i < 4; i++) s[nc][i] = 0.0f;

        #pragma unroll
        for (int kc = 0; kc < 8; kc++) {
            unsigned a[4];
            a[0] = Qs[(row0 + g) * QP + kc * 8 + tig];
            a[1] = Qs[(row0 + g + 8) * QP + kc * 8 + tig];
            a[2] = Qs[(row0 + g) * QP + kc * 8 + tig + 4];
            a[3] = Qs[(row0 + g + 8) * QP + kc * 8 + tig + 4];
            #pragma unroll
            for (int nc = 0; nc < 8; nc++) {
                unsigned b[2];
                b[0] = Ks[(nc * 8 + g) * QP + kc * 8 + tig];
                b[1] = Ks[(nc * 8 + g) * QP + kc * 8 + tig + 4];
                mma_tf32(s[nc], a, b);
            }
        }

        // scale + causal mask on diagonal block
        #pragma unroll
        for (int nc = 0; nc < 8; nc++)
            #pragma unroll
            for (int i = 0; i < 4; i++) s[nc][i] *= 0.125f;

        if (jb == qb) {
            int r_lo = row0 + g, r_hi = row0 + g + 8;
            #pragma unroll
            for (int nc = 0; nc < 8; nc++) {
                int c0 = nc * 8 + 2 * tig, c1 = c0 + 1;
                if (c0 > r_lo) s[nc][0] = -1e30f;
                if (c1 > r_lo) s[nc][1] = -1e30f;
                if (c0 > r_hi) s[nc][2] = -1e30f;
                if (c1 > r_hi) s[nc][3] = -1e30f;
            }
        }

        // row max (local over 16 cols, then across the 4-lane quad)
        float mx0 = -1e30f, mx1 = -1e30f;
        #pragma unroll
        for (int nc = 0; nc < 8; nc++) {
            mx0 = fmaxf(mx0, fmaxf(s[nc][0], s[nc][1]));
            mx1 = fmaxf(mx1, fmaxf(s[nc][2], s[nc][3]));
        }
        mx0 = fmaxf(mx0, __shfl_xor_sync(0xffffffffu, mx0, 1));
        mx0 = fmaxf(mx0, __shfl_xor_sync(0xffffffffu, mx0, 2));
        mx1 = fmaxf(mx1, __shfl_xor_sync(0xffffffffu, mx1, 1));
        mx1 = fmaxf(mx1, __shfl_xor_sync(0xffffffffu, mx1, 2));

        float mn0 = fmaxf(m0, mx0), mn1 = fmaxf(m1, mx1);
        float al0 = __expf(m0 - mn0), al1 = __expf(m1 - mn1);

        float rs0 = 0.0f, rs1 = 0.0f;
        #pragma unroll
        for (int nc = 0; nc < 8; nc++) {
            float p0 = __expf(s[nc][0] - mn0);
            float p1 = __expf(s[nc][1] - mn0);
            float p2 = __expf(s[nc][2] - mn1);
            float p3 = __expf(s[nc][3] - mn1);
            rs0 += p0 + p1;
            rs1 += p2 + p3;
            uint2 lo = make_uint2(f2tf(p0), f2tf(p1));
            uint2 hi = make_uint2(f2tf(p2), f2tf(p3));
            *(uint2*)&Ps[(row0 + g) * QP + nc * 8 + 2 * tig]     = lo;
            *(uint2*)&Ps[(row0 + g + 8) * QP + nc * 8 + 2 * tig] = hi;
        }
        rs0 += __shfl_xor_sync(0xffffffffu, rs0, 1);
        rs0 += __shfl_xor_sync(0xffffffffu, rs0, 2);
        rs1 += __shfl_xor_sync(0xffffffffu, rs1, 1);
        rs1 += __shfl_xor_sync(0xffffffffu, rs1, 2);

        l0 = l0 * al0 + rs0;
        l1 = l1 * al1 + rs1;
        m0 = mn0;
        m1 = mn1;
        #pragma unroll
        for (int nc = 0; nc < 8; nc++) {
            o[nc][0] *= al0; o[nc][1] *= al0;
            o[nc][2] *= al1; o[nc][3] *= al1;
        }
        __syncwarp();  // Ps rows are warp-private; make stores visible in-warp

        // ---- O += P @ V ----
        #pragma unroll
        for (int kc = 0; kc < 8; kc++) {
            unsigned a[4];
            a[0] = Ps[(row0 + g) * QP + kc * 8 + tig];
            a[1] = Ps[(row0 + g + 8) * QP + kc * 8 + tig];
            a[2] = Ps[(row0 + g) * QP + kc * 8 + tig + 4];
            a[3] = Ps[(row0 + g + 8) * QP + kc * 8 + tig + 4];
            #pragma unroll
            for (int nc = 0; nc < 8; nc++) {
                unsigned b[2];
                b[0] = Vs[(kc * 8 + tig) * VP + nc * 8 + g];
                b[1] = Vs[(kc * 8 + tig + 4) * VP + nc * 8 + g];
                mma_tf32(o[nc], a, b);
            }
        }
    }

    // Normalize and write ctx
    float inv0 = 1.0f / l0, inv1 = 1.0f / l1;
    #pragma unroll
    for (int nc = 0; nc < 8; nc++) {
        int col = h * HDIM + nc * 8 + 2 * tig;
        int r_lo = qb * 64 + row0 + g;
        float2 lo = make_float2(o[nc][0] * inv0, o[nc][1] * inv0);
        float2 hi = make_float2(o[nc][2] * inv1, o[nc][3] * inv1);
        *(float2*)&g_ctx[(size_t)r_lo * DMODEL + col]       = lo;
        *(float2*)&g_ctx[(size_t)(r_lo + 8) * DMODEL + col] = hi;
    }
}

// ---------------------------------------------------------------------------
extern "C" void kernel_launch(void* const* d_in, const int* in_sizes, int n_in,
                              void* d_out, int out_size) {
    (void)in_sizes; (void)n_in; (void)out_size;
    const float* x     = (const float*)d_in[0];
    const float* w_qkv = (const float*)d_in[1];
    const float* b_qkv = (const float*)d_in[2];
    const float* w_out = (const float*)d_in[3];
    const float* b_out = (const float*)d_in[4];
    float* out = (float*)d_out;

    float* qkv_ptr = nullptr;
    float* ctx_ptr = nullptr;
    cudaGetSymbolAddress((void**)&qkv_ptr, g_qkv);
    cudaGetSymbolAddress((void**)&ctx_ptr, g_ctx);

    const int ATTN_SMEM = (3 * 64 * QP + 64 * VP) * (int)sizeof(unsigned);  // 70656 B
    static bool attr_set = false;
    if (!attr_set) {
        cudaFuncSetAttribute(attn_tf32_kernel,
                             cudaFuncAttributeMaxDynamicSharedMemorySize, ATTN_SMEM);
        attr_set = true;
    }

    // 1) QKV projection
    gemm_tf32_kernel<<<dim3(QKV_N / 128, SEQ / 128), 256>>>(
        x, w_qkv, b_qkv, qkv_ptr, SEQ, QKV_N, DMODEL);

    // 2) Causal attention
    attn_tf32_kernel<<<dim3(SEQ / 64, NHEADS), 128, ATTN_SMEM>>>();

    // 3) Output projection
    gemm_tf32_kernel<<<dim3(DMODEL / 128, SEQ / 128), 256>>>(
        ctx_ptr, w_out, b_out, out, SEQ, DMODEL, DMODEL);
}